// round 4
// baseline (speedup 1.0000x reference)
#include <cuda_runtime.h>
#include <cstdint>
#include <cstddef>

#define DK 128
#define NMAX 100000
#define MT 64
#define AP 132
#define GEMM_THREADS 256

// Scratch (device globals: no allocation allowed). float4-typed for 16B base alignment.
__device__ float4 g_agg_st4[(size_t)NMAX * (DK / 4)];
__device__ float4 g_agg_ts4[(size_t)NMAX * (DK / 4)];
__device__ float g_cnt_in[NMAX];
__device__ float g_cnt_out[NMAX];
__device__ float g_inv_in[NMAX];
__device__ float g_inv_out[NMAX];

__global__ void zero_kernel(int n_nodes) {
    int stride = gridDim.x * blockDim.x;
    int i0 = blockIdx.x * blockDim.x + threadIdx.x;
    int total4 = n_nodes * (DK / 4);
    float4 z = make_float4(0.f, 0.f, 0.f, 0.f);
    for (int i = i0; i < total4; i += stride) {
        g_agg_st4[i] = z;
        g_agg_ts4[i] = z;
    }
    for (int i = i0; i < n_nodes; i += stride) {
        g_cnt_in[i] = 0.f;
        g_cnt_out[i] = 0.f;
    }
}

// One warp per edge, BOTH directions. Lane l owns floats [4l, 4l+4).
// edge_index is INT32 (JAX x64 disabled -> jnp.int64 request silently int32).
// Vector red.global.add.v4.f32: one 16B reduction message per lane per
// direction (vs 4 scalar REDGs) -> 4x fewer L2 atomic-ALU ops.
__global__ void scatter_kernel(const float* __restrict__ x,
                               const int* __restrict__ ei, int E) {
    int e = (int)((blockIdx.x * (unsigned)blockDim.x + threadIdx.x) >> 5);
    int lane = threadIdx.x & 31;
    if (e >= E) return;
    int s = ei[e];        // edge_index[0][e] (src)
    int d = ei[E + e];    // edge_index[1][e] (dst)
    float4 vs = __ldg(((const float4*)(x + (size_t)s * DK)) + lane);
    float4 vd = __ldg(((const float4*)(x + (size_t)d * DK)) + lane);
    float4* pst = g_agg_st4 + (size_t)d * (DK / 4) + lane;  // src -> dst mean
    float4* pts = g_agg_ts4 + (size_t)s * (DK / 4) + lane;  // dst -> src mean
    asm volatile("red.global.add.v4.f32 [%0], {%1, %2, %3, %4};"
                 :: "l"(pst), "f"(vs.x), "f"(vs.y), "f"(vs.z), "f"(vs.w) : "memory");
    asm volatile("red.global.add.v4.f32 [%0], {%1, %2, %3, %4};"
                 :: "l"(pts), "f"(vd.x), "f"(vd.y), "f"(vd.z), "f"(vd.w) : "memory");
    if (lane == 0) {
        atomicAdd(g_cnt_in + d, 1.0f);
        atomicAdd(g_cnt_out + s, 1.0f);
    }
}

// inv = 0.5 / max(count, 1): folds the alpha blend weight into the mean.
__global__ void inv_kernel(int n) {
    int i = blockIdx.x * blockDim.x + threadIdx.x;
    if (i < n) {
        g_inv_in[i]  = 0.5f / fmaxf(g_cnt_in[i], 1.f);
        g_inv_out[i] = 0.5f / fmaxf(g_cnt_out[i], 1.f);
    }
}

// Fused GEMM: out = x@Wlin + (agg_st*inv_in)@Wst + (agg_ts*inv_out)@Wts + b_comb.
// Inner product uses packed fma.rn.f32x2 (2 FMAs per issue slot on sm_103a).
__global__ void __launch_bounds__(GEMM_THREADS, 2) gemm_kernel(
    const float* __restrict__ x,
    const float* __restrict__ Wlin, const float* __restrict__ Wst, const float* __restrict__ Wts,
    const float* __restrict__ blin, const float* __restrict__ bst, const float* __restrict__ bts,
    float* __restrict__ out, int N)
{
    extern __shared__ float smem[];
    float* Ws = smem;                 // [DK][DK] row-major (k-major)
    float* As = smem + DK * DK;       // [MT][AP], AP=132 kills bank conflicts
    int tid = threadIdx.x;
    int txc = tid & 15;               // column group: cols txc*8 .. +7
    int ty  = tid >> 4;               // row group:    rows ty*4 .. +3
    int row0 = blockIdx.x * MT;

    unsigned long long acc[4][4];     // [row][colpair], packed (f32,f32)
#pragma unroll
    for (int r = 0; r < 4; r++)
#pragma unroll
        for (int p = 0; p < 4; p++) acc[r][p] = 0ull;

#pragma unroll 1
    for (int seg = 0; seg < 3; seg++) {
        const float* W   = seg == 0 ? Wlin : (seg == 1 ? Wst : Wts);
        const float4* A4 = seg == 0 ? (const float4*)x
                                    : (seg == 1 ? (const float4*)g_agg_st4
                                                : (const float4*)g_agg_ts4);
        const float* inv = (seg == 1) ? g_inv_in : g_inv_out;
        __syncthreads();
#pragma unroll
        for (int i = 0; i < 16; i++) {
            int idx = tid + i * GEMM_THREADS;
            ((float4*)Ws)[idx] = __ldg(((const float4*)W) + idx);
        }
#pragma unroll
        for (int i = 0; i < 8; i++) {
            int idx = tid + i * GEMM_THREADS;
            int r = idx >> 5, kc = idx & 31;
            int rg = row0 + r;
            float4 v = make_float4(0.f, 0.f, 0.f, 0.f);
            if (rg < N) {
                v = __ldg(A4 + (size_t)rg * (DK / 4) + kc);
                if (seg) {
                    float sc = inv[rg];
                    v.x *= sc; v.y *= sc; v.z *= sc; v.w *= sc;
                }
            }
            *((float4*)(As + r * AP + (kc << 2))) = v;
        }
        __syncthreads();
#pragma unroll 8
        for (int k = 0; k < DK; k++) {
            ulonglong2 w0 = *((const ulonglong2*)(Ws + k * DK + txc * 8));
            ulonglong2 w1 = *((const ulonglong2*)(Ws + k * DK + txc * 8 + 4));
#pragma unroll
            for (int r = 0; r < 4; r++) {
                float a = As[(ty * 4 + r) * AP + k];
                unsigned long long ap;
                asm("mov.b64 %0, {%1, %1};" : "=l"(ap) : "f"(a));
                asm("fma.rn.f32x2 %0, %1, %2, %3;" : "=l"(acc[r][0]) : "l"(ap), "l"(w0.x), "l"(acc[r][0]));
                asm("fma.rn.f32x2 %0, %1, %2, %3;" : "=l"(acc[r][1]) : "l"(ap), "l"(w0.y), "l"(acc[r][1]));
                asm("fma.rn.f32x2 %0, %1, %2, %3;" : "=l"(acc[r][2]) : "l"(ap), "l"(w1.x), "l"(acc[r][2]));
                asm("fma.rn.f32x2 %0, %1, %2, %3;" : "=l"(acc[r][3]) : "l"(ap), "l"(w1.y), "l"(acc[r][3]));
            }
        }
    }

    // Epilogue: combined bias + store
    int c0 = txc * 8;
    float4 bl0 = __ldg((const float4*)(blin + c0));
    float4 bl1 = __ldg((const float4*)(blin + c0 + 4));
    float4 bs0 = __ldg((const float4*)(bst + c0));
    float4 bs1 = __ldg((const float4*)(bst + c0 + 4));
    float4 bt0 = __ldg((const float4*)(bts + c0));
    float4 bt1 = __ldg((const float4*)(bts + c0 + 4));
    float bb[8];
    bb[0] = bl0.x + 0.5f * (bs0.x + bt0.x);
    bb[1] = bl0.y + 0.5f * (bs0.y + bt0.y);
    bb[2] = bl0.z + 0.5f * (bs0.z + bt0.z);
    bb[3] = bl0.w + 0.5f * (bs0.w + bt0.w);
    bb[4] = bl1.x + 0.5f * (bs1.x + bt1.x);
    bb[5] = bl1.y + 0.5f * (bs1.y + bt1.y);
    bb[6] = bl1.z + 0.5f * (bs1.z + bt1.z);
    bb[7] = bl1.w + 0.5f * (bs1.w + bt1.w);

#pragma unroll
    for (int r = 0; r < 4; r++) {
        int rg = row0 + ty * 4 + r;
        if (rg < N) {
            float o[8];
#pragma unroll
            for (int p = 0; p < 4; p++)
                asm("mov.b64 {%0, %1}, %2;" : "=f"(o[2 * p]), "=f"(o[2 * p + 1]) : "l"(acc[r][p]));
            float4 o0 = make_float4(o[0] + bb[0], o[1] + bb[1], o[2] + bb[2], o[3] + bb[3]);
            float4 o1 = make_float4(o[4] + bb[4], o[5] + bb[5], o[6] + bb[6], o[7] + bb[7]);
            *((float4*)(out + (size_t)rg * DK + c0)) = o0;
            *((float4*)(out + (size_t)rg * DK + c0 + 4)) = o1;
        }
    }
}

extern "C" void kernel_launch(void* const* d_in, const int* in_sizes, int n_in,
                              void* d_out, int out_size) {
    const float* x    = (const float*)d_in[0];
    const int*   ei   = (const int*)d_in[1];      // int32! (JAX x64 disabled)
    const float* Wlin = (const float*)d_in[2];
    const float* blin = (const float*)d_in[3];
    const float* Wst  = (const float*)d_in[4];
    const float* bst  = (const float*)d_in[5];
    const float* Wts  = (const float*)d_in[6];
    const float* bts  = (const float*)d_in[7];
    float* out = (float*)d_out;
    int N = in_sizes[0] / DK;
    int E = in_sizes[1] / 2;

    zero_kernel<<<1024, 256>>>(N);

    long long total_threads = (long long)E * 32;
    int blocks = (int)((total_threads + 255) / 256);
    scatter_kernel<<<blocks, 256>>>(x, ei, E);

    inv_kernel<<<(N + 255) / 256, 256>>>(N);

    const int SMEM = (DK * DK + MT * AP) * (int)sizeof(float);
    cudaFuncSetAttribute(gemm_kernel, cudaFuncAttributeMaxDynamicSharedMemorySize, SMEM);
    gemm_kernel<<<(N + MT - 1) / MT, GEMM_THREADS, SMEM>>>(
        x, Wlin, Wst, Wts, blin, bst, bts, out, N);
}